// round 2
// baseline (speedup 1.0000x reference)
#include <cuda_runtime.h>

#define NPTS 16384
#define CDIM 64
#define ODIM 128
#define KNN  16

// ---------------- scratch (no allocation allowed) ----------------
__device__ float g_base[NPTS * ODIM];   // x @ (W1a - W1b) + b1
__device__ float g_Bv[NPTS * ODIM];     // x @ W1b
__device__ float g_sq[NPTS];            // |x|^2
__device__ int   g_idx[NPTS * KNN];     // knn indices

// =================================================================
// precompute: base, Bv, sq.  4 points per block, 128 threads (o=tid)
// =================================================================
__global__ void __launch_bounds__(128) precompute_kernel(
    const float* __restrict__ x, const float* __restrict__ W1,
    const float* __restrict__ b1)
{
    const int n0  = blockIdx.x * 4;
    const int tid = threadIdx.x;
    __shared__ float xs[4][64];

    #pragma unroll
    for (int r = 0; r < 2; r++) {
        int li = r * 128 + tid;
        xs[li >> 6][li & 63] = x[n0 * 64 + li];
    }
    __syncthreads();

    float a1[4] = {0.f, 0.f, 0.f, 0.f};
    float a2[4] = {0.f, 0.f, 0.f, 0.f};
    #pragma unroll 4
    for (int c = 0; c < 64; c++) {
        float wa = W1[c * 128 + tid];
        float wb = W1[(64 + c) * 128 + tid];
        float wd = wa - wb;
        #pragma unroll
        for (int nn = 0; nn < 4; nn++) {
            float xv = xs[nn][c];
            a1[nn] = fmaf(xv, wd, a1[nn]);
            a2[nn] = fmaf(xv, wb, a2[nn]);
        }
    }
    float bb = b1[tid];
    #pragma unroll
    for (int nn = 0; nn < 4; nn++) {
        g_base[(n0 + nn) * 128 + tid] = a1[nn] + bb;
        g_Bv[(n0 + nn) * 128 + tid]  = a2[nn];
    }

    int w = tid >> 5, lane = tid & 31;
    float v = xs[w][lane] * xs[w][lane] + xs[w][lane + 32] * xs[w][lane + 32];
    #pragma unroll
    for (int off = 16; off > 0; off >>= 1)
        v += __shfl_xor_sync(0xffffffffu, v, off);
    if (lane == 0) g_sq[n0 + w] = v;
}

// =================================================================
// kNN: 64 queries x 128 j per CTA tile, 256 CTAs (one wave at 2/SM).
// Thread = 8 queries x 4 j accumulators -> 32 FFMA per 3 LDS.128.
// score = xi.xj - 0.5|xj|^2 (appended row), top-16 kept in registers.
// =================================================================
#define JT   128
#define JSTR 132
// dynamic smem layout (floats):
//   xiT: [65][64]   = 4160   (row 64 = -0.5 constant)
//   xjT: [33][128]  = 4224   (row 32 = |xj|^2 during half 1)
//   dst: [64][132]  = 8448
#define OFF_XJ 4160
#define OFF_DS 8384
#define SM_FLOATS 16832
#define SM_BYTES  (SM_FLOATS * 4)

#define TOPK_INSERT(valx, jjx) do {                                        \
    float _d = (valx); int _j = (jjx);                                     \
    if (_d < kd[15]) {                                                     \
        _Pragma("unroll")                                                  \
        for (int _m = 0; _m < 16; _m++) {                                  \
            if (_d < kd[_m]) {                                             \
                float _td = kd[_m]; kd[_m] = _d; _d = _td;                 \
                int   _tj = ki[_m]; ki[_m] = _j; _j = _tj;                 \
            }                                                              \
        }                                                                  \
    }                                                                      \
} while (0)

__global__ void __launch_bounds__(256, 2) knn_kernel(const float* __restrict__ x)
{
    extern __shared__ __align__(16) float sm[];
    float* xiT = sm;
    float* xjT = sm + OFF_XJ;
    float* dst = sm + OFF_DS;

    const int tid = threadIdx.x;
    const int q0  = blockIdx.x * 64;

    // ---- load query tile transposed: xiT[c][i], row 64 = -0.5 ----
    {
        const int il = tid & 63, cq = (tid >> 6) * 16;
        const float4* src = (const float4*)(x + (q0 + il) * 64 + cq);
        #pragma unroll
        for (int u4 = 0; u4 < 4; u4++) {
            float4 v = src[u4];
            xiT[(cq + u4 * 4 + 0) * 64 + il] = v.x;
            xiT[(cq + u4 * 4 + 1) * 64 + il] = v.y;
            xiT[(cq + u4 * 4 + 2) * 64 + il] = v.z;
            xiT[(cq + u4 * 4 + 3) * 64 + il] = v.w;
        }
        if (tid < 64) xiT[64 * 64 + tid] = -0.5f;
    }

    const int ty = tid >> 5;          // warp id: query block (8 queries)
    const int tx = tid & 31;          // j block (4 j)
    const int qs = tid >> 2, sl = tid & 3;   // scan: query, j-slice (32 wide)

    float kd[16]; int ki[16];
    #pragma unroll
    for (int m = 0; m < 16; m++) { kd[m] = 1e30f; ki[m] = 0; }

    __syncthreads();

    const int jl = tid & 127;              // j point this thread stages
    const int ch = (tid >> 7) * 16;        // c sub-range (0 or 16)

    for (int tile = 0; tile < NPTS / JT; tile++) {
        const int j0 = tile * JT;
        float acc[8][4];
        #pragma unroll
        for (int r = 0; r < 8; r++)
            #pragma unroll
            for (int s = 0; s < 4; s++) acc[r][s] = 0.f;

        // ---- stage half 0: c = 0..31 (transposed) ----
        {
            const float4* src = (const float4*)(x + (j0 + jl) * 64 + ch);
            #pragma unroll
            for (int u4 = 0; u4 < 4; u4++) {
                float4 v = src[u4];
                xjT[(ch + u4 * 4 + 0) * JT + jl] = v.x;
                xjT[(ch + u4 * 4 + 1) * JT + jl] = v.y;
                xjT[(ch + u4 * 4 + 2) * JT + jl] = v.z;
                xjT[(ch + u4 * 4 + 3) * JT + jl] = v.w;
            }
        }
        __syncthreads();
        #pragma unroll 8
        for (int c = 0; c < 32; c++) {
            float4 a0 = *(const float4*)&xiT[c * 64 + ty * 8];
            float4 a1 = *(const float4*)&xiT[c * 64 + ty * 8 + 4];
            float4 b  = *(const float4*)&xjT[c * JT + tx * 4];
            float ar[8] = {a0.x, a0.y, a0.z, a0.w, a1.x, a1.y, a1.z, a1.w};
            float bs[4] = {b.x, b.y, b.z, b.w};
            #pragma unroll
            for (int r = 0; r < 8; r++)
                #pragma unroll
                for (int s = 0; s < 4; s++)
                    acc[r][s] = fmaf(ar[r], bs[s], acc[r][s]);
        }
        __syncthreads();

        // ---- stage half 1: c = 32..63, row 32 = |xj|^2 ----
        {
            const float4* src = (const float4*)(x + (j0 + jl) * 64 + 32 + ch);
            #pragma unroll
            for (int u4 = 0; u4 < 4; u4++) {
                float4 v = src[u4];
                xjT[(ch + u4 * 4 + 0) * JT + jl] = v.x;
                xjT[(ch + u4 * 4 + 1) * JT + jl] = v.y;
                xjT[(ch + u4 * 4 + 2) * JT + jl] = v.z;
                xjT[(ch + u4 * 4 + 3) * JT + jl] = v.w;
            }
            if (tid < 128) xjT[32 * JT + tid] = g_sq[j0 + tid];
        }
        __syncthreads();
        #pragma unroll 8
        for (int c = 0; c < 32; c++) {
            float4 a0 = *(const float4*)&xiT[(32 + c) * 64 + ty * 8];
            float4 a1 = *(const float4*)&xiT[(32 + c) * 64 + ty * 8 + 4];
            float4 b  = *(const float4*)&xjT[c * JT + tx * 4];
            float ar[8] = {a0.x, a0.y, a0.z, a0.w, a1.x, a1.y, a1.z, a1.w};
            float bs[4] = {b.x, b.y, b.z, b.w};
            #pragma unroll
            for (int r = 0; r < 8; r++)
                #pragma unroll
                for (int s = 0; s < 4; s++)
                    acc[r][s] = fmaf(ar[r], bs[s], acc[r][s]);
        }
        {   // c = 64: score row, ar = -0.5 constant, b = |xj|^2
            float4 b = *(const float4*)&xjT[32 * JT + tx * 4];
            float bs[4] = {b.x, b.y, b.z, b.w};
            #pragma unroll
            for (int r = 0; r < 8; r++)
                #pragma unroll
                for (int s = 0; s < 4; s++)
                    acc[r][s] = fmaf(-0.5f, bs[s], acc[r][s]);
        }

        // negate -> smaller == closer; stage to smem for per-query scan
        #pragma unroll
        for (int r = 0; r < 8; r++) {
            float4 v = make_float4(-acc[r][0], -acc[r][1], -acc[r][2], -acc[r][3]);
            *(float4*)&dst[(ty * 8 + r) * JSTR + tx * 4] = v;
        }
        __syncthreads();

        // ---- scan my 32-wide slice of my query's row ----
        #pragma unroll
        for (int m4 = 0; m4 < 8; m4++) {
            float4 v = *(const float4*)&dst[qs * JSTR + sl * 32 + m4 * 4];
            int jb = j0 + sl * 32 + m4 * 4;
            TOPK_INSERT(v.x, jb + 0);
            TOPK_INSERT(v.y, jb + 1);
            TOPK_INSERT(v.z, jb + 2);
            TOPK_INSERT(v.w, jb + 3);
        }
        __syncthreads();
    }

    // ---- merge 4 sorted 16-lists per query ----
    float* candd = sm;                     // 4096 floats
    int*   candi = (int*)(sm + 4096);      // 4096 ints
    #pragma unroll
    for (int m = 0; m < 16; m++) {
        candd[tid * 16 + m] = kd[m];
        candi[tid * 16 + m] = ki[m];
    }
    __syncthreads();
    if (tid < 64) {
        int p[4] = {0, 0, 0, 0};
        const int ob = (q0 + tid) * 16;
        #pragma unroll
        for (int m = 0; m < 16; m++) {
            float best = 1e30f; int bsl = 0;
            #pragma unroll
            for (int s = 0; s < 4; s++) {
                float v = (p[s] < 16) ? candd[(tid * 4 + s) * 16 + p[s]] : 1e30f;
                if (v < best) { best = v; bsl = s; }
            }
            g_idx[ob + m] = candi[(tid * 4 + bsl) * 16 + p[bsl]];
            p[bsl]++;
        }
    }
}

// =================================================================
// aggregate: s = mean_k relu(base + Bv[j_k]);  out = s @ W2 + b2
// 8 points per block, 128 threads (o = tid), W2 read coalesced.
// =================================================================
__global__ void __launch_bounds__(128) aggregate_kernel(
    const float* __restrict__ W2, const float* __restrict__ b2,
    float* __restrict__ out)
{
    const int n0  = blockIdx.x * 8;
    const int tid = threadIdx.x;
    __shared__ float ss[8][128];
    __shared__ int sidx[128];

    sidx[tid] = g_idx[n0 * 16 + tid];      // 8 * 16 = 128
    __syncthreads();

    #pragma unroll
    for (int p = 0; p < 8; p++) {
        float bv  = g_base[(n0 + p) * 128 + tid];
        float acc = 0.f;
        #pragma unroll
        for (int k = 0; k < 16; k++) {
            float v = bv + g_Bv[sidx[p * 16 + k] * 128 + tid];
            acc += fmaxf(v, 0.f);
        }
        ss[p][tid] = acc * (1.0f / 16.0f);
    }
    __syncthreads();

    float r[8];
    float bb = b2[tid];
    #pragma unroll
    for (int p = 0; p < 8; p++) r[p] = bb;

    #pragma unroll 4
    for (int i = 0; i < 128; i++) {
        float w = W2[i * 128 + tid];
        #pragma unroll
        for (int p = 0; p < 8; p++)
            r[p] = fmaf(ss[p][i], w, r[p]);
    }
    #pragma unroll
    for (int p = 0; p < 8; p++)
        out[(n0 + p) * 128 + tid] = r[p];
}

// =================================================================
extern "C" void kernel_launch(void* const* d_in, const int* in_sizes, int n_in,
                              void* d_out, int out_size)
{
    const float* x  = (const float*)d_in[0];
    const float* W1 = (const float*)d_in[1];
    const float* b1 = (const float*)d_in[2];
    const float* W2 = (const float*)d_in[3];
    const float* b2 = (const float*)d_in[4];
    float* out = (float*)d_out;

    cudaFuncSetAttribute(knn_kernel,
                         cudaFuncAttributeMaxDynamicSharedMemorySize, SM_BYTES);

    precompute_kernel<<<NPTS / 4, 128>>>(x, W1, b1);
    knn_kernel<<<NPTS / 64, 256, SM_BYTES>>>(x);
    aggregate_kernel<<<NPTS / 8, 128>>>(W2, b2, out);
}

// round 3
// speedup vs baseline: 1.0209x; 1.0209x over previous
#include <cuda_runtime.h>
#include <cuda_bf16.h>

#define NPTS 16384
#define ODIM 128
#define KNN  16
#define NBLK 128          // 16384 / 128

// ---------------- scratch (no allocation allowed) ----------------
__device__ float g_base[NPTS * ODIM];              // x @ (W1a - W1b) + b1
__device__ float g_Bv[NPTS * ODIM];                // x @ W1b
__device__ __align__(16) float g_sq[NPTS];         // |x|^2
__device__ int   g_idx[NPTS * KNN];                // knn indices
__device__ __align__(16) unsigned g_Af[NBLK * 8192];  // A fragments (bf16x2)
__device__ __align__(16) unsigned g_Bf[NBLK * 8192];  // B fragments (bf16x2)

// =================================================================
// precompute: base, Bv, sq.  4 points per block, 128 threads (o=tid)
// =================================================================
__global__ void __launch_bounds__(128) precompute_kernel(
    const float* __restrict__ x, const float* __restrict__ W1,
    const float* __restrict__ b1)
{
    const int n0  = blockIdx.x * 4;
    const int tid = threadIdx.x;
    __shared__ float xs[4][64];

    #pragma unroll
    for (int r = 0; r < 2; r++) {
        int li = r * 128 + tid;
        xs[li >> 6][li & 63] = x[n0 * 64 + li];
    }
    __syncthreads();

    float a1[4] = {0.f, 0.f, 0.f, 0.f};
    float a2[4] = {0.f, 0.f, 0.f, 0.f};
    #pragma unroll 4
    for (int c = 0; c < 64; c++) {
        float wa = W1[c * 128 + tid];
        float wb = W1[(64 + c) * 128 + tid];
        float wd = wa - wb;
        #pragma unroll
        for (int nn = 0; nn < 4; nn++) {
            float xv = xs[nn][c];
            a1[nn] = fmaf(xv, wd, a1[nn]);
            a2[nn] = fmaf(xv, wb, a2[nn]);
        }
    }
    float bb = b1[tid];
    #pragma unroll
    for (int nn = 0; nn < 4; nn++) {
        g_base[(n0 + nn) * 128 + tid] = a1[nn] + bb;
        g_Bv[(n0 + nn) * 128 + tid]  = a2[nn];
    }

    int w = tid >> 5, lane = tid & 31;
    float v = xs[w][lane] * xs[w][lane] + xs[w][lane + 32] * xs[w][lane + 32];
    #pragma unroll
    for (int off = 16; off > 0; off >>= 1)
        v += __shfl_xor_sync(0xffffffffu, v, off);
    if (lane == 0) g_sq[n0 + w] = v;
}

// =================================================================
// fragpack: split x into bf16 hi/lo and store in mma fragment order.
// A frag layout (per 128-pt block, u32 idx): ((sel*4+ks)*8+mt)*128 + lane*4 + r
// B frag layout:                             ((sel*4+ks)*16+nt)*64 + lane*2 + r
// m16n8k16: lane = g*4+cb (g=row&7, cb=(k>>1)&3)
//   A: r = ((k>>3)&1)*2 + ((row>>3)&1)      B: r = (k>>3)&1
// =================================================================
__global__ void __launch_bounds__(256) fragpack_kernel(const float* __restrict__ x)
{
    extern __shared__ unsigned smu[];
    unsigned* sA = smu;            // 8192
    unsigned* sB = smu + 8192;     // 8192

    const int blk = blockIdx.x;
    const int tid = threadIdx.x;
    const int rl  = tid >> 1;            // local point 0..127
    const int c0  = (tid & 1) * 32;      // column half

    float v[32];
    const float4* xr = (const float4*)(x + (blk * 128 + rl) * 64 + c0);
    #pragma unroll
    for (int i = 0; i < 8; i++) {
        float4 t = xr[i];
        v[i * 4 + 0] = t.x; v[i * 4 + 1] = t.y;
        v[i * 4 + 2] = t.z; v[i * 4 + 3] = t.w;
    }

    const int mt = rl >> 4, gid = rl & 7, r0 = (rl >> 3) & 1;
    const int nt = rl >> 3;
    const int l  = gid * 4;  // + cb below

    #pragma unroll
    for (int cc = 0; cc < 32; cc += 2) {
        int c = c0 + cc;
        float f0 = v[cc], f1 = v[cc + 1];
        __nv_bfloat16 h0 = __float2bfloat16(f0);
        __nv_bfloat16 h1 = __float2bfloat16(f1);
        __nv_bfloat16 l0 = __float2bfloat16(f0 - __bfloat162float(h0));
        __nv_bfloat16 l1 = __float2bfloat16(f1 - __bfloat162float(h1));
        unsigned uhi = ((unsigned)__bfloat16_as_ushort(h1) << 16) | __bfloat16_as_ushort(h0);
        unsigned ulo = ((unsigned)__bfloat16_as_ushort(l1) << 16) | __bfloat16_as_ushort(l0);

        int ks = c >> 4, cb = (c >> 1) & 3, r1 = (c >> 3) & 1;
        int la = l + cb;
        int rA = r1 * 2 + r0;
        sA[((0 * 4 + ks) * 8 + mt) * 128 + la * 4 + rA] = uhi;
        sA[((1 * 4 + ks) * 8 + mt) * 128 + la * 4 + rA] = ulo;
        sB[((0 * 4 + ks) * 16 + nt) * 64 + la * 2 + r1] = uhi;
        sB[((1 * 4 + ks) * 16 + nt) * 64 + la * 2 + r1] = ulo;
    }
    __syncthreads();

    uint4* dA = (uint4*)(g_Af + blk * 8192);
    uint4* dB = (uint4*)(g_Bf + blk * 8192);
    const uint4* s4A = (const uint4*)sA;
    const uint4* s4B = (const uint4*)sB;
    #pragma unroll
    for (int i = 0; i < 8; i++) {
        dA[i * 256 + tid] = s4A[i * 256 + tid];
        dB[i * 256 + tid] = s4B[i * 256 + tid];
    }
}

// =================================================================
// kNN via bf16 tensor-core GEMM (4-term hi/lo split, fp32 accum).
// CTA: 128 queries x all j in tiles of 128. 8 warps, each 64x32.
// =================================================================
// smem u32 layout:
#define OFF_B   8192            // B double buffer: 2 x 8192
#define OFF_SQ  24576           // 2 x 128 floats
#define OFF_DST 24832           // 128 x 132 floats
#define SM_U32  41728
#define SM_BYTES (SM_U32 * 4)
#define DSTR 132

#define TOPK_INSERT(valx, jjx) do {                                        \
    float _d = (valx); int _j = (jjx);                                     \
    if (_d < kd[15]) {                                                     \
        _Pragma("unroll")                                                  \
        for (int _m = 0; _m < 16; _m++) {                                  \
            if (_d < kd[_m]) {                                             \
                float _td = kd[_m]; kd[_m] = _d; _d = _td;                 \
                int   _tj = ki[_m]; ki[_m] = _j; _j = _tj;                 \
            }                                                              \
        }                                                                  \
    }                                                                      \
} while (0)

__device__ __forceinline__ void cp16(unsigned saddr, const void* g)
{
    asm volatile("cp.async.cg.shared.global [%0], [%1], 16;" :: "r"(saddr), "l"(g));
}

__global__ void __launch_bounds__(256, 1) knn_kernel()
{
    extern __shared__ __align__(16) unsigned sm[];
    float* dstf = (float*)(sm + OFF_DST);

    const int tid  = threadIdx.x;
    const int lane = tid & 31;
    const int wid  = tid >> 5;
    const int wm   = wid >> 2;       // 0..1 : m-block of 64 rows
    const int wn   = wid & 3;        // 0..3 : n-block of 32 cols
    const unsigned smbase = (unsigned)__cvta_generic_to_shared(sm);

    // ---- initial loads: A block + B tile 0 + sq 0 ----
    {
        const uint4* gA = (const uint4*)(g_Af + blockIdx.x * 8192);
        #pragma unroll
        for (int i = 0; i < 8; i++)
            cp16(smbase + (i * 1024 + tid * 4) * 4, gA + i * 256 + tid);
        const uint4* gB = (const uint4*)(g_Bf);
        #pragma unroll
        for (int i = 0; i < 8; i++)
            cp16(smbase + (OFF_B + i * 1024 + tid * 4) * 4, gB + i * 256 + tid);
        if (tid < 32)
            cp16(smbase + (OFF_SQ + tid * 4) * 4, g_sq + tid * 4);
    }
    asm volatile("cp.async.commit_group;");

    float kd[16]; int ki[16];
    #pragma unroll
    for (int m = 0; m < 16; m++) { kd[m] = 1e30f; ki[m] = 0; }

    const int qh = tid & 1;          // scan: which half of the row
    const int qq = tid >> 1;         // scan: query row

    for (int jt = 0; jt < NBLK; jt++) {
        const int cur = jt & 1;
        // ---- prefetch next B tile ----
        if (jt + 1 < NBLK) {
            const uint4* gB = (const uint4*)(g_Bf + (jt + 1) * 8192);
            #pragma unroll
            for (int i = 0; i < 8; i++)
                cp16(smbase + (OFF_B + ((jt + 1) & 1) * 8192 + i * 1024 + tid * 4) * 4,
                     gB + i * 256 + tid);
            if (tid < 32)
                cp16(smbase + (OFF_SQ + ((jt + 1) & 1) * 128 + tid * 4) * 4,
                     g_sq + (jt + 1) * 128 + tid * 4);
        }
        asm volatile("cp.async.commit_group;");
        asm volatile("cp.async.wait_group 1;");
        __syncthreads();

        // ---- MMA: 16 k-steps over (Ahi/Alo) x (Bhi/Blo) ----
        float acc[4][4][4];
        #pragma unroll
        for (int mi = 0; mi < 4; mi++)
            #pragma unroll
            for (int ni = 0; ni < 4; ni++)
                #pragma unroll
                for (int r = 0; r < 4; r++) acc[mi][ni][r] = 0.f;

        #pragma unroll
        for (int kk = 0; kk < 16; kk++) {
            const int sa = (kk >> 2) & 1, sb = kk >> 3, ks = kk & 3;
            const uint4* Ab = (const uint4*)(sm + ((sa * 4 + ks) * 8 + wm * 4) * 128);
            const uint2* Bb = (const uint2*)(sm + OFF_B + cur * 8192 +
                                             ((sb * 4 + ks) * 16 + wn * 4) * 64);
            unsigned a[4][4], b[4][2];
            #pragma unroll
            for (int mi = 0; mi < 4; mi++) {
                uint4 t = Ab[mi * 32 + lane];
                a[mi][0] = t.x; a[mi][1] = t.y; a[mi][2] = t.z; a[mi][3] = t.w;
            }
            #pragma unroll
            for (int ni = 0; ni < 4; ni++) {
                uint2 t = Bb[ni * 32 + lane];
                b[ni][0] = t.x; b[ni][1] = t.y;
            }
            #pragma unroll
            for (int mi = 0; mi < 4; mi++)
                #pragma unroll
                for (int ni = 0; ni < 4; ni++)
                    asm volatile(
                        "mma.sync.aligned.m16n8k16.row.col.f32.bf16.bf16.f32 "
                        "{%0,%1,%2,%3}, {%4,%5,%6,%7}, {%8,%9}, {%0,%1,%2,%3};"
                        : "+f"(acc[mi][ni][0]), "+f"(acc[mi][ni][1]),
                          "+f"(acc[mi][ni][2]), "+f"(acc[mi][ni][3])
                        : "r"(a[mi][0]), "r"(a[mi][1]), "r"(a[mi][2]), "r"(a[mi][3]),
                          "r"(b[ni][0]), "r"(b[ni][1]));
        }

        // ---- epilogue: score = 0.5*|xj|^2 - dot, stage to smem ----
        const float* sqb = (const float*)(sm + OFF_SQ + cur * 128);
        const int g  = lane >> 2;
        const int c2 = (lane & 3) * 2;
        #pragma unroll
        for (int mi = 0; mi < 4; mi++) {
            #pragma unroll
            for (int ni = 0; ni < 4; ni++) {
                int row = (wm * 4 + mi) * 16 + g;
                int col = (wn * 4 + ni) * 8 + c2;
                float q0 = 0.5f * sqb[col], q1 = 0.5f * sqb[col + 1];
                float2 s0 = make_float2(q0 - acc[mi][ni][0], q1 - acc[mi][ni][1]);
                float2 s1 = make_float2(q0 - acc[mi][ni][2], q1 - acc[mi][ni][3]);
                *(float2*)&dstf[row * DSTR + col] = s0;
                *(float2*)&dstf[(row + 8) * DSTR + col] = s1;
            }
        }
        __syncthreads();

        // ---- scan my 64-wide half-row, maintain top-16 ----
        const int j0 = jt * 128;
        #pragma unroll
        for (int m4 = 0; m4 < 16; m4++) {
            float4 v = *(const float4*)&dstf[qq * DSTR + qh * 64 + m4 * 4];
            int jb = j0 + qh * 64 + m4 * 4;
            TOPK_INSERT(v.x, jb + 0);
            TOPK_INSERT(v.y, jb + 1);
            TOPK_INSERT(v.z, jb + 2);
            TOPK_INSERT(v.w, jb + 3);
        }
        __syncthreads();
    }

    // ---- merge 2 sorted 16-lists per query ----
    float* candd = dstf;
    int*   candi = (int*)(dstf + 4096);
    #pragma unroll
    for (int m = 0; m < 16; m++) {
        candd[tid * 16 + m] = kd[m];
        candi[tid * 16 + m] = ki[m];
    }
    __syncthreads();
    if (tid < 128) {
        int p0 = 0, p1 = 0;
        const int ob = (blockIdx.x * 128 + tid) * 16;
        #pragma unroll
        for (int m = 0; m < 16; m++) {
            float v0 = candd[(tid * 2) * 16 + p0];
            float v1 = candd[(tid * 2 + 1) * 16 + p1];
            if (v0 <= v1) { g_idx[ob + m] = candi[(tid * 2) * 16 + p0]; p0++; }
            else          { g_idx[ob + m] = candi[(tid * 2 + 1) * 16 + p1]; p1++; }
        }
    }
}

// =================================================================
// aggregate: s = mean_k relu(base + Bv[j_k]);  out = s @ W2 + b2
// 8 points per block, 128 threads (o = tid), W2 read coalesced.
// =================================================================
__global__ void __launch_bounds__(128) aggregate_kernel(
    const float* __restrict__ W2, const float* __restrict__ b2,
    float* __restrict__ out)
{
    const int n0  = blockIdx.x * 8;
    const int tid = threadIdx.x;
    __shared__ float ss[8][128];
    __shared__ int sidx[128];

    sidx[tid] = g_idx[n0 * 16 + tid];
    __syncthreads();

    #pragma unroll
    for (int p = 0; p < 8; p++) {
        float bv  = g_base[(n0 + p) * 128 + tid];
        float acc = 0.f;
        #pragma unroll
        for (int k = 0; k < 16; k++) {
            float v = bv + g_Bv[sidx[p * 16 + k] * 128 + tid];
            acc += fmaxf(v, 0.f);
        }
        ss[p][tid] = acc * (1.0f / 16.0f);
    }
    __syncthreads();

    float r[8];
    float bb = b2[tid];
    #pragma unroll
    for (int p = 0; p < 8; p++) r[p] = bb;

    #pragma unroll 4
    for (int i = 0; i < 128; i++) {
        float w = W2[i * 128 + tid];
        #pragma unroll
        for (int p = 0; p < 8; p++)
            r[p] = fmaf(ss[p][i], w, r[p]);
    }
    #pragma unroll
    for (int p = 0; p < 8; p++)
        out[(n0 + p) * 128 + tid] = r[p];
}

// =================================================================
extern "C" void kernel_launch(void* const* d_in, const int* in_sizes, int n_in,
                              void* d_out, int out_size)
{
    const float* x  = (const float*)d_in[0];
    const float* W1 = (const float*)d_in[1];
    const float* b1 = (const float*)d_in[2];
    const float* W2 = (const float*)d_in[3];
    const float* b2 = (const float*)d_in[4];
    float* out = (float*)d_out;

    cudaFuncSetAttribute(fragpack_kernel,
                         cudaFuncAttributeMaxDynamicSharedMemorySize, 65536);
    cudaFuncSetAttribute(knn_kernel,
                         cudaFuncAttributeMaxDynamicSharedMemorySize, SM_BYTES);

    precompute_kernel<<<NPTS / 4, 128>>>(x, W1, b1);
    fragpack_kernel<<<NBLK, 256, 65536>>>(x);
    knn_kernel<<<NBLK, 256, SM_BYTES>>>();
    aggregate_kernel<<<NPTS / 8, 128>>>(W2, b2, out);
}